// round 16
// baseline (speedup 1.0000x reference)
#include <cuda_runtime.h>
#include <cuda_fp16.h>
#include <cstdint>

#define NROWS 409600
#define NIN   51200
#define NSEG  65536
#define DIM   512
#define NGB   4096                 // gather blocks (16 segments each)
#define NMT   512                  // mtiles (128 segments each)

// ---------------- scratch (static __device__ arrays: alloc-free rule) ----------
__device__ int    g_is64 = 1;       // detect only ever writes 0 -> replay-deterministic
__device__ int    g_counts[NSEG];
__device__ int    g_part[256];
__device__ int    g_pbase[256];
__device__ int    g_offsets[NSEG];
__device__ int    g_cursor[NSEG];
__device__ int    g_perm[NROWS];
__device__ int    g_mdone[NMT];     // per-mtile gather-completion counters (0..8)
__device__ __half g_aggh[(size_t)NSEG * DIM];   // 67 MB, fp16-rounded segment sums
__device__ __half g_linwh[DIM * DIM];           // fp16 copy of lin_w

// ---------------- helpers ----------------
__device__ __forceinline__ int load_idx(const void* idx, int i, int is64) {
    if (is64) return (int)((const long long*)idx)[i];
    return ((const int*)idx)[i];
}
__device__ __forceinline__ void cp16(uint32_t smem, const void* gmem) {
    asm volatile("cp.async.cg.shared.global [%0], [%1], 16;"
                 :: "r"(smem), "l"(gmem) : "memory");
}

// ---------------- prep kernels ----------------
__global__ void zero_detect_roundw_kernel(const unsigned int* w32,
                                          const float* __restrict__ lw) {
    int i = blockIdx.x * blockDim.x + threadIdx.x;
    if (i < NSEG) g_counts[i] = 0;
    if (i < NMT) g_mdone[i] = 0;
    if (i < 1024 && w32[2 * i + 1] != 0u) g_is64 = 0;
    if (i < DIM * DIM) g_linwh[i] = __float2half_rn(lw[i]);
}
__global__ void hist_kernel(const void* idx) {
    int i = blockIdx.x * blockDim.x + threadIdx.x;
    if (i >= NROWS) return;
    atomicAdd(&g_counts[load_idx(idx, i, g_is64)], 1);
}
__global__ void scan1_kernel() {
    __shared__ int ws[8];
    int t = threadIdx.x;
    int v = g_counts[blockIdx.x * 256 + t];
    #pragma unroll
    for (int o = 16; o > 0; o >>= 1) v += __shfl_down_sync(0xFFFFFFFFu, v, o);
    if ((t & 31) == 0) ws[t >> 5] = v;
    __syncthreads();
    if (t == 0) {
        int s = 0;
        #pragma unroll
        for (int k = 0; k < 8; k++) s += ws[k];
        g_part[blockIdx.x] = s;
    }
}
__global__ void scan2_kernel() {
    __shared__ int ws[8];
    int t = threadIdx.x, lane = t & 31, wid = t >> 5;
    int v = g_part[t];
    int x = v;
    #pragma unroll
    for (int o = 1; o < 32; o <<= 1) {
        int y = __shfl_up_sync(0xFFFFFFFFu, x, o);
        if (lane >= o) x += y;
    }
    if (lane == 31) ws[wid] = x;
    __syncthreads();
    if (t < 8) {
        int s = ws[t];
        #pragma unroll
        for (int o = 1; o < 8; o <<= 1) {
            int y = __shfl_up_sync(0xFFu, s, o);
            if (t >= o) s += y;
        }
        ws[t] = s;
    }
    __syncthreads();
    int base = (wid > 0) ? ws[wid - 1] : 0;
    g_pbase[t] = base + x - v;
}
__global__ void scan3_kernel() {
    __shared__ int ws[8];
    int t = threadIdx.x, lane = t & 31, wid = t >> 5;
    int i = blockIdx.x * 256 + t;
    int v = g_counts[i];
    int x = v;
    #pragma unroll
    for (int o = 1; o < 32; o <<= 1) {
        int y = __shfl_up_sync(0xFFFFFFFFu, x, o);
        if (lane >= o) x += y;
    }
    if (lane == 31) ws[wid] = x;
    __syncthreads();
    if (t < 8) {
        int s = ws[t];
        #pragma unroll
        for (int o = 1; o < 8; o <<= 1) {
            int y = __shfl_up_sync(0xFFu, s, o);
            if (t >= o) s += y;
        }
        ws[t] = s;
    }
    __syncthreads();
    int base = (wid > 0) ? ws[wid - 1] : 0;
    int off = g_pbase[blockIdx.x] + base + x - v;
    g_offsets[i] = off;
    g_cursor[i]  = off;
}
__global__ void scatter_kernel(const void* idx) {
    int i = blockIdx.x * blockDim.x + threadIdx.x;
    if (i >= NROWS) return;
    int s = load_idx(idx, i, g_is64);
    int pos = atomicAdd(&g_cursor[s], 1);
    g_perm[pos] = i;
}

// ---------------- fused gather + GEMM (producer-consumer via flags) ------------
#define BK 64
#define PADH 72
#define ATILEB (128 * PADH * 2)            // 18432 bytes
#define BTILEB (256 * PADH * 2)            // 36864 bytes
#define SMEM_BYTES (2 * ATILEB + 2 * BTILEB)   // 110592

__device__ __forceinline__ void mma_f16(float& d0, float& d1, float& d2, float& d3,
                                        uint32_t a0, uint32_t a1, uint32_t a2, uint32_t a3,
                                        uint32_t b0, uint32_t b1) {
    asm volatile(
        "mma.sync.aligned.m16n8k16.row.col.f32.f16.f16.f32 "
        "{%0,%1,%2,%3}, {%4,%5,%6,%7}, {%8,%9}, {%0,%1,%2,%3};"
        : "+f"(d0), "+f"(d1), "+f"(d2), "+f"(d3)
        : "r"(a0), "r"(a1), "r"(a2), "r"(a3), "r"(b0), "r"(b1));
}

__device__ void gather_role(const float* __restrict__ h, const float* __restrict__ w,
                            int tid, int bid) {
    int wid = tid >> 5, lane = tid & 31;
    int seg = bid * 16 + wid;
    int start = g_offsets[seg];
    int cnt   = g_counts[seg];
    float4 a0 = {0.f, 0.f, 0.f, 0.f}, a1 = a0, a2 = a0, a3 = a0;
    const float4* hb = (const float4*)h;

    auto fma_row = [&](float wv, float4 x0, float4 x1, float4 x2, float4 x3) {
        a0.x = fmaf(wv, x0.x, a0.x); a0.y = fmaf(wv, x0.y, a0.y);
        a0.z = fmaf(wv, x0.z, a0.z); a0.w = fmaf(wv, x0.w, a0.w);
        a1.x = fmaf(wv, x1.x, a1.x); a1.y = fmaf(wv, x1.y, a1.y);
        a1.z = fmaf(wv, x1.z, a1.z); a1.w = fmaf(wv, x1.w, a1.w);
        a2.x = fmaf(wv, x2.x, a2.x); a2.y = fmaf(wv, x2.y, a2.y);
        a2.z = fmaf(wv, x2.z, a2.z); a2.w = fmaf(wv, x2.w, a2.w);
        a3.x = fmaf(wv, x3.x, a3.x); a3.y = fmaf(wv, x3.y, a3.y);
        a3.z = fmaf(wv, x3.z, a3.z); a3.w = fmaf(wv, x3.w, a3.w);
    };
    auto accum4 = [&](int r0, int r1, int r2, int r3) {
        float w0 = __ldg(&w[r0 % NIN]);
        float w1 = __ldg(&w[r1 % NIN]);
        float w2 = __ldg(&w[r2 % NIN]);
        float w3 = __ldg(&w[r3 % NIN]);
        const float4* p0 = hb + (size_t)r0 * (DIM / 4);
        const float4* p1 = hb + (size_t)r1 * (DIM / 4);
        const float4* p2 = hb + (size_t)r2 * (DIM / 4);
        const float4* p3 = hb + (size_t)r3 * (DIM / 4);
        float4 x00 = __ldg(p0 + lane),      x01 = __ldg(p0 + 32 + lane);
        float4 x02 = __ldg(p0 + 64 + lane), x03 = __ldg(p0 + 96 + lane);
        float4 x10 = __ldg(p1 + lane),      x11 = __ldg(p1 + 32 + lane);
        float4 x12 = __ldg(p1 + 64 + lane), x13 = __ldg(p1 + 96 + lane);
        float4 x20 = __ldg(p2 + lane),      x21 = __ldg(p2 + 32 + lane);
        float4 x22 = __ldg(p2 + 64 + lane), x23 = __ldg(p2 + 96 + lane);
        float4 x30 = __ldg(p3 + lane),      x31 = __ldg(p3 + 32 + lane);
        float4 x32 = __ldg(p3 + 64 + lane), x33 = __ldg(p3 + 96 + lane);
        fma_row(w0, x00, x01, x02, x03);
        fma_row(w1, x10, x11, x12, x13);
        fma_row(w2, x20, x21, x22, x23);
        fma_row(w3, x30, x31, x32, x33);
    };
    auto accum2 = [&](int r0, int r1) {
        float w0 = __ldg(&w[r0 % NIN]);
        float w1 = __ldg(&w[r1 % NIN]);
        const float4* p0 = hb + (size_t)r0 * (DIM / 4);
        const float4* p1 = hb + (size_t)r1 * (DIM / 4);
        float4 x00 = __ldg(p0 + lane),      x01 = __ldg(p0 + 32 + lane);
        float4 x02 = __ldg(p0 + 64 + lane), x03 = __ldg(p0 + 96 + lane);
        float4 x10 = __ldg(p1 + lane),      x11 = __ldg(p1 + 32 + lane);
        float4 x12 = __ldg(p1 + 64 + lane), x13 = __ldg(p1 + 96 + lane);
        fma_row(w0, x00, x01, x02, x03);
        fma_row(w1, x10, x11, x12, x13);
    };
    auto accum1 = [&](int r0) {
        float w0 = __ldg(&w[r0 % NIN]);
        const float4* p0 = hb + (size_t)r0 * (DIM / 4);
        float4 x00 = __ldg(p0 + lane),      x01 = __ldg(p0 + 32 + lane);
        float4 x02 = __ldg(p0 + 64 + lane), x03 = __ldg(p0 + 96 + lane);
        fma_row(w0, x00, x01, x02, x03);
    };

    if (cnt <= 32) {
        int v = (lane < cnt) ? g_perm[start + lane] : 0x7FFFFFFF;
        #pragma unroll
        for (int k = 2; k <= 32; k <<= 1) {
            #pragma unroll
            for (int j = k >> 1; j > 0; j >>= 1) {
                int p = __shfl_xor_sync(0xFFFFFFFFu, v, j);
                bool up = ((lane & k) == 0);
                bool lower = ((lane & j) == 0);
                v = (lower == up) ? min(v, p) : max(v, p);
            }
        }
        int j = 0;
        for (; j + 4 <= cnt; j += 4) {
            int r0 = __shfl_sync(0xFFFFFFFFu, v, j);
            int r1 = __shfl_sync(0xFFFFFFFFu, v, j + 1);
            int r2 = __shfl_sync(0xFFFFFFFFu, v, j + 2);
            int r3 = __shfl_sync(0xFFFFFFFFu, v, j + 3);
            accum4(r0, r1, r2, r3);
        }
        if (j + 2 <= cnt) {
            int r0 = __shfl_sync(0xFFFFFFFFu, v, j);
            int r1 = __shfl_sync(0xFFFFFFFFu, v, j + 1);
            accum2(r0, r1);
            j += 2;
        }
        if (j < cnt) accum1(__shfl_sync(0xFFFFFFFFu, v, j));
    } else if (cnt <= 256) {
        int vals[8];
        int nslot = (cnt + 31) >> 5;
        #pragma unroll
        for (int t = 0; t < 8; t++) {
            int p = t * 32 + lane;
            vals[t] = (t < nslot && p < cnt) ? g_perm[start + p] : 0x7FFFFFFF;
        }
        for (int it = 0; it < cnt; it++) {
            int m = 0x7FFFFFFF, mt = -1;
            #pragma unroll
            for (int t = 0; t < 8; t++)
                if (vals[t] < m) { m = vals[t]; mt = t; }
            int gm = __reduce_min_sync(0xFFFFFFFFu, m);
            if (m == gm && mt >= 0) vals[mt] = 0x7FFFFFFF;
            accum1(gm);
        }
    } else {
        for (int j = 0; j < cnt; j++) accum1(g_perm[start + j]);
    }

    __half2* dsth = (__half2*)(g_aggh + (size_t)seg * DIM);
    dsth[2 * lane]           = __floats2half2_rn(a0.x, a0.y);
    dsth[2 * lane + 1]       = __floats2half2_rn(a0.z, a0.w);
    dsth[64 + 2 * lane]      = __floats2half2_rn(a1.x, a1.y);
    dsth[64 + 2 * lane + 1]  = __floats2half2_rn(a1.z, a1.w);
    dsth[128 + 2 * lane]     = __floats2half2_rn(a2.x, a2.y);
    dsth[128 + 2 * lane + 1] = __floats2half2_rn(a2.z, a2.w);
    dsth[192 + 2 * lane]     = __floats2half2_rn(a3.x, a3.y);
    dsth[192 + 2 * lane + 1] = __floats2half2_rn(a3.z, a3.w);
}

__device__ void gemm_role(const float* __restrict__ linb, float* __restrict__ out,
                          char* sm, int tid, int gi) {
    int lane = tid & 31, wid = tid >> 5;
    int ntile = gi & 1, mtile = gi >> 1;

    // wait for this mtile's 8 gather blocks (release by atomicAdd after threadfence)
    if (tid == 0) {
        while (*((volatile int*)&g_mdone[mtile]) < 8) __nanosleep(200);
        __threadfence();
    }
    __syncthreads();

    const __half* Ag = g_aggh  + (size_t)mtile * 128 * DIM;
    const __half* Bg = g_linwh + (size_t)ntile * 256 * DIM;
    uint32_t sbase = (uint32_t)__cvta_generic_to_shared(sm);

    auto load_tile = [&](int kb, int buf) {
        uint32_t as = sbase + (uint32_t)(buf * ATILEB);
        uint32_t bs = sbase + (uint32_t)(2 * ATILEB + buf * BTILEB);
        #pragma unroll
        for (int j = 0; j < 2; j++) {      // A: 128 rows x 64 halves = 1024 x 16B
            int e = j * 512 + tid;
            int row = e >> 3, c = e & 7;
            cp16(as + (uint32_t)(row * PADH + c * 8) * 2,
                 Ag + (size_t)row * DIM + kb * BK + c * 8);
        }
        #pragma unroll
        for (int j = 0; j < 4; j++) {      // B: 256 rows x 64 halves = 2048 x 16B
            int e = j * 512 + tid;
            int n = e >> 3, c = e & 7;
            cp16(bs + (uint32_t)(n * PADH + c * 8) * 2,
                 Bg + (size_t)n * DIM + kb * BK + c * 8);
        }
        asm volatile("cp.async.commit_group;" ::: "memory");
    };

    int wm = (wid & 1) * 64;
    int wn = (wid >> 1) * 32;
    float acc[4][4][4];
    #pragma unroll
    for (int mi = 0; mi < 4; mi++)
        #pragma unroll
        for (int ni = 0; ni < 4; ni++)
            #pragma unroll
            for (int q = 0; q < 4; q++) acc[mi][ni][q] = 0.f;

    load_tile(0, 0);
    const int NKB = DIM / BK;              // 8
    int rq = lane >> 2, cq = lane & 3;
    for (int kb = 0; kb < NKB; kb++) {
        if (kb + 1 < NKB) {
            load_tile(kb + 1, (kb + 1) & 1);
            asm volatile("cp.async.wait_group 1;" ::: "memory");
        } else {
            asm volatile("cp.async.wait_group 0;" ::: "memory");
        }
        __syncthreads();

        int buf = kb & 1;
        const uint32_t* As = (const uint32_t*)(sm + buf * ATILEB);
        const uint32_t* Bs = (const uint32_t*)(sm + 2 * ATILEB + buf * BTILEB);
        #pragma unroll
        for (int ks = 0; ks < BK / 16; ks++) {     // 4 K-steps of 16 halves
            int k0 = ks * 8;
            uint32_t bf[4][2];
            #pragma unroll
            for (int ni = 0; ni < 4; ni++) {
                int n = wn + ni * 8 + rq;
                bf[ni][0] = Bs[n * (PADH / 2) + k0 + cq];
                bf[ni][1] = Bs[n * (PADH / 2) + k0 + cq + 4];
            }
            #pragma unroll
            for (int mi = 0; mi < 4; mi++) {
                int r = wm + mi * 16 + rq;
                uint32_t fa0 = As[r * (PADH / 2) + k0 + cq];
                uint32_t fa1 = As[(r + 8) * (PADH / 2) + k0 + cq];
                uint32_t fa2 = As[r * (PADH / 2) + k0 + cq + 4];
                uint32_t fa3 = As[(r + 8) * (PADH / 2) + k0 + cq + 4];
                #pragma unroll
                for (int ni = 0; ni < 4; ni++)
                    mma_f16(acc[mi][ni][0], acc[mi][ni][1], acc[mi][ni][2], acc[mi][ni][3],
                            fa0, fa1, fa2, fa3, bf[ni][0], bf[ni][1]);
            }
        }
        __syncthreads();
    }

    #pragma unroll
    for (int mi = 0; mi < 4; mi++) {
        int r0 = mtile * 128 + wm + mi * 16 + rq;
        #pragma unroll
        for (int ni = 0; ni < 4; ni++) {
            int col = ntile * 256 + wn + ni * 8 + 2 * cq;
            float2 bv = __ldg((const float2*)(linb + col));
            float2 v0 = {acc[mi][ni][0] + bv.x, acc[mi][ni][1] + bv.y};
            float2 v1 = {acc[mi][ni][2] + bv.x, acc[mi][ni][3] + bv.y};
            *(float2*)(out + (size_t)r0 * DIM + col) = v0;
            *(float2*)(out + (size_t)(r0 + 8) * DIM + col) = v1;
        }
    }
}

__global__ void __launch_bounds__(512, 1)
fused_gg_kernel(const float* __restrict__ h, const float* __restrict__ w,
                const float* __restrict__ linb, float* __restrict__ out) {
    extern __shared__ char sm[];
    int tid = threadIdx.x;
    int bid = blockIdx.x;
    if (bid < NGB) {
        gather_role(h, w, tid, bid);
        __syncthreads();                 // all 16 segment-warps of this block done
        __threadfence();                 // publish g_aggh before the flag
        if (tid == 0) atomicAdd(&g_mdone[bid >> 3], 1);
    } else {
        gemm_role(linb, out, sm, tid, bid - NGB);
    }
}

// ---------------- launch ----------------
extern "C" void kernel_launch(void* const* d_in, const int* in_sizes, int n_in,
                              void* d_out, int out_size) {
    const float* h     = (const float*)d_in[0];
    const float* w     = (const float*)d_in[1];
    const float* lin_w = (const float*)d_in[2];
    const float* lin_b = (const float*)d_in[3];
    const void*  idx   = d_in[4];
    float* out = (float*)d_out;

    zero_detect_roundw_kernel<<<(DIM * DIM + 255) / 256, 256>>>(
        (const unsigned int*)idx, lin_w);
    hist_kernel<<<(NROWS + 255) / 256, 256>>>(idx);
    scan1_kernel<<<256, 256>>>();
    scan2_kernel<<<1, 256>>>();
    scan3_kernel<<<256, 256>>>();
    scatter_kernel<<<(NROWS + 255) / 256, 256>>>(idx);

    static int smem_set = 0;
    if (!smem_set) {
        cudaFuncSetAttribute(fused_gg_kernel, cudaFuncAttributeMaxDynamicSharedMemorySize,
                             SMEM_BYTES);
        smem_set = 1;
    }
    fused_gg_kernel<<<NGB + 2 * NMT, 512, SMEM_BYTES>>>(h, w, lin_b, out);
}

// round 17
// speedup vs baseline: 1.1595x; 1.1595x over previous
#include <cuda_runtime.h>
#include <cuda_fp16.h>
#include <cstdint>

#define NROWS 409600
#define NIN   51200
#define NSEG  65536
#define DIM   512
#define NGB   8192                 // gather blocks (8 segments each)
#define NGEMM 2048                 // gemm blocks (mtile x 4 ntiles)
#define LEAD  592                  // gather blocks before first gemm in bid order

// ---------------- scratch (static __device__ arrays: alloc-free rule) ----------
__device__ int    g_is64 = 1;       // detect only ever writes 0 -> replay-deterministic
__device__ int    g_counts[NSEG];
__device__ int    g_part[256];
__device__ int    g_pbase[256];
__device__ int    g_offsets[NSEG];
__device__ int    g_cursor[NSEG];
__device__ int    g_perm[NROWS];
__device__ int    g_mdone[512];     // per-mtile completed-segment counters (0..128)
__device__ __half g_aggh[(size_t)NSEG * DIM];   // 67 MB, fp16-rounded segment sums
__device__ __half g_linwh[DIM * DIM];           // fp16 copy of lin_w

// ---------------- helpers ----------------
__device__ __forceinline__ int load_idx(const void* idx, int i, int is64) {
    if (is64) return (int)((const long long*)idx)[i];
    return ((const int*)idx)[i];
}
__device__ __forceinline__ void cp16(uint32_t smem, const void* gmem) {
    asm volatile("cp.async.cg.shared.global [%0], [%1], 16;"
                 :: "r"(smem), "l"(gmem) : "memory");
}

// ---------------- prep kernels ----------------
__global__ void zero_detect_roundw_kernel(const unsigned int* w32,
                                          const float* __restrict__ lw) {
    int i = blockIdx.x * blockDim.x + threadIdx.x;
    if (i < NSEG) g_counts[i] = 0;
    if (i < 512) g_mdone[i] = 0;
    if (i < 1024 && w32[2 * i + 1] != 0u) g_is64 = 0;
    if (i < DIM * DIM) g_linwh[i] = __float2half_rn(lw[i]);
}
__global__ void hist_kernel(const void* idx) {
    int i = blockIdx.x * blockDim.x + threadIdx.x;
    if (i >= NROWS) return;
    atomicAdd(&g_counts[load_idx(idx, i, g_is64)], 1);
}
__global__ void scan1_kernel() {
    __shared__ int ws[8];
    int t = threadIdx.x;
    int v = g_counts[blockIdx.x * 256 + t];
    #pragma unroll
    for (int o = 16; o > 0; o >>= 1) v += __shfl_down_sync(0xFFFFFFFFu, v, o);
    if ((t & 31) == 0) ws[t >> 5] = v;
    __syncthreads();
    if (t == 0) {
        int s = 0;
        #pragma unroll
        for (int k = 0; k < 8; k++) s += ws[k];
        g_part[blockIdx.x] = s;
    }
}
__global__ void scan2_kernel() {
    __shared__ int ws[8];
    int t = threadIdx.x, lane = t & 31, wid = t >> 5;
    int v = g_part[t];
    int x = v;
    #pragma unroll
    for (int o = 1; o < 32; o <<= 1) {
        int y = __shfl_up_sync(0xFFFFFFFFu, x, o);
        if (lane >= o) x += y;
    }
    if (lane == 31) ws[wid] = x;
    __syncthreads();
    if (t < 8) {
        int s = ws[t];
        #pragma unroll
        for (int o = 1; o < 8; o <<= 1) {
            int y = __shfl_up_sync(0xFFu, s, o);
            if (t >= o) s += y;
        }
        ws[t] = s;
    }
    __syncthreads();
    int base = (wid > 0) ? ws[wid - 1] : 0;
    g_pbase[t] = base + x - v;
}
__global__ void scan3_kernel() {
    __shared__ int ws[8];
    int t = threadIdx.x, lane = t & 31, wid = t >> 5;
    int i = blockIdx.x * 256 + t;
    int v = g_counts[i];
    int x = v;
    #pragma unroll
    for (int o = 1; o < 32; o <<= 1) {
        int y = __shfl_up_sync(0xFFFFFFFFu, x, o);
        if (lane >= o) x += y;
    }
    if (lane == 31) ws[wid] = x;
    __syncthreads();
    if (t < 8) {
        int s = ws[t];
        #pragma unroll
        for (int o = 1; o < 8; o <<= 1) {
            int y = __shfl_up_sync(0xFFu, s, o);
            if (t >= o) s += y;
        }
        ws[t] = s;
    }
    __syncthreads();
    int base = (wid > 0) ? ws[wid - 1] : 0;
    int off = g_pbase[blockIdx.x] + base + x - v;
    g_offsets[i] = off;
    g_cursor[i]  = off;
}
__global__ void scatter_kernel(const void* idx) {
    int i = blockIdx.x * blockDim.x + threadIdx.x;
    if (i >= NROWS) return;
    int s = load_idx(idx, i, g_is64);
    int pos = atomicAdd(&g_cursor[s], 1);
    g_perm[pos] = i;
}

// ---------------- fused gather + GEMM (interleaved producer-consumer) ----------
#define BK 64
#define PADH 72
#define ATILEB (128 * PADH * 2)            // 18432 bytes
#define BTILEB (128 * PADH * 2)            // 18432 bytes
#define SMEM_BYTES (2 * ATILEB + 2 * BTILEB)   // 73728 -> 2 blocks/SM

__device__ __forceinline__ void mma_f16(float& d0, float& d1, float& d2, float& d3,
                                        uint32_t a0, uint32_t a1, uint32_t a2, uint32_t a3,
                                        uint32_t b0, uint32_t b1) {
    asm volatile(
        "mma.sync.aligned.m16n8k16.row.col.f32.f16.f16.f32 "
        "{%0,%1,%2,%3}, {%4,%5,%6,%7}, {%8,%9}, {%0,%1,%2,%3};"
        : "+f"(d0), "+f"(d1), "+f"(d2), "+f"(d3)
        : "r"(a0), "r"(a1), "r"(a2), "r"(a3), "r"(b0), "r"(b1));
}

// one warp processes one segment; publishes its own flag, no block barrier
__device__ void gather_role(const float* __restrict__ h, const float* __restrict__ w,
                            int tid, int gb) {
    int wid = tid >> 5, lane = tid & 31;
    int seg = gb * 8 + wid;
    int start = g_offsets[seg];
    int cnt   = g_counts[seg];
    float4 a0 = {0.f, 0.f, 0.f, 0.f}, a1 = a0, a2 = a0, a3 = a0;
    const float4* hb = (const float4*)h;

    auto fma_row = [&](float wv, float4 x0, float4 x1, float4 x2, float4 x3) {
        a0.x = fmaf(wv, x0.x, a0.x); a0.y = fmaf(wv, x0.y, a0.y);
        a0.z = fmaf(wv, x0.z, a0.z); a0.w = fmaf(wv, x0.w, a0.w);
        a1.x = fmaf(wv, x1.x, a1.x); a1.y = fmaf(wv, x1.y, a1.y);
        a1.z = fmaf(wv, x1.z, a1.z); a1.w = fmaf(wv, x1.w, a1.w);
        a2.x = fmaf(wv, x2.x, a2.x); a2.y = fmaf(wv, x2.y, a2.y);
        a2.z = fmaf(wv, x2.z, a2.z); a2.w = fmaf(wv, x2.w, a2.w);
        a3.x = fmaf(wv, x3.x, a3.x); a3.y = fmaf(wv, x3.y, a3.y);
        a3.z = fmaf(wv, x3.z, a3.z); a3.w = fmaf(wv, x3.w, a3.w);
    };
    auto accum4 = [&](int r0, int r1, int r2, int r3) {
        float w0 = __ldg(&w[r0 % NIN]);
        float w1 = __ldg(&w[r1 % NIN]);
        float w2 = __ldg(&w[r2 % NIN]);
        float w3 = __ldg(&w[r3 % NIN]);
        const float4* p0 = hb + (size_t)r0 * (DIM / 4);
        const float4* p1 = hb + (size_t)r1 * (DIM / 4);
        const float4* p2 = hb + (size_t)r2 * (DIM / 4);
        const float4* p3 = hb + (size_t)r3 * (DIM / 4);
        float4 x00 = __ldg(p0 + lane),      x01 = __ldg(p0 + 32 + lane);
        float4 x02 = __ldg(p0 + 64 + lane), x03 = __ldg(p0 + 96 + lane);
        float4 x10 = __ldg(p1 + lane),      x11 = __ldg(p1 + 32 + lane);
        float4 x12 = __ldg(p1 + 64 + lane), x13 = __ldg(p1 + 96 + lane);
        float4 x20 = __ldg(p2 + lane),      x21 = __ldg(p2 + 32 + lane);
        float4 x22 = __ldg(p2 + 64 + lane), x23 = __ldg(p2 + 96 + lane);
        float4 x30 = __ldg(p3 + lane),      x31 = __ldg(p3 + 32 + lane);
        float4 x32 = __ldg(p3 + 64 + lane), x33 = __ldg(p3 + 96 + lane);
        fma_row(w0, x00, x01, x02, x03);
        fma_row(w1, x10, x11, x12, x13);
        fma_row(w2, x20, x21, x22, x23);
        fma_row(w3, x30, x31, x32, x33);
    };
    auto accum2 = [&](int r0, int r1) {
        float w0 = __ldg(&w[r0 % NIN]);
        float w1 = __ldg(&w[r1 % NIN]);
        const float4* p0 = hb + (size_t)r0 * (DIM / 4);
        const float4* p1 = hb + (size_t)r1 * (DIM / 4);
        float4 x00 = __ldg(p0 + lane),      x01 = __ldg(p0 + 32 + lane);
        float4 x02 = __ldg(p0 + 64 + lane), x03 = __ldg(p0 + 96 + lane);
        float4 x10 = __ldg(p1 + lane),      x11 = __ldg(p1 + 32 + lane);
        float4 x12 = __ldg(p1 + 64 + lane), x13 = __ldg(p1 + 96 + lane);
        fma_row(w0, x00, x01, x02, x03);
        fma_row(w1, x10, x11, x12, x13);
    };
    auto accum1 = [&](int r0) {
        float w0 = __ldg(&w[r0 % NIN]);
        const float4* p0 = hb + (size_t)r0 * (DIM / 4);
        float4 x00 = __ldg(p0 + lane),      x01 = __ldg(p0 + 32 + lane);
        float4 x02 = __ldg(p0 + 64 + lane), x03 = __ldg(p0 + 96 + lane);
        fma_row(w0, x00, x01, x02, x03);
    };

    if (cnt <= 32) {
        int v = (lane < cnt) ? g_perm[start + lane] : 0x7FFFFFFF;
        #pragma unroll
        for (int k = 2; k <= 32; k <<= 1) {
            #pragma unroll
            for (int j = k >> 1; j > 0; j >>= 1) {
                int p = __shfl_xor_sync(0xFFFFFFFFu, v, j);
                bool up = ((lane & k) == 0);
                bool lower = ((lane & j) == 0);
                v = (lower == up) ? min(v, p) : max(v, p);
            }
        }
        int j = 0;
        for (; j + 4 <= cnt; j += 4) {
            int r0 = __shfl_sync(0xFFFFFFFFu, v, j);
            int r1 = __shfl_sync(0xFFFFFFFFu, v, j + 1);
            int r2 = __shfl_sync(0xFFFFFFFFu, v, j + 2);
            int r3 = __shfl_sync(0xFFFFFFFFu, v, j + 3);
            accum4(r0, r1, r2, r3);
        }
        if (j + 2 <= cnt) {
            int r0 = __shfl_sync(0xFFFFFFFFu, v, j);
            int r1 = __shfl_sync(0xFFFFFFFFu, v, j + 1);
            accum2(r0, r1);
            j += 2;
        }
        if (j < cnt) accum1(__shfl_sync(0xFFFFFFFFu, v, j));
    } else if (cnt <= 256) {
        int vals[8];
        int nslot = (cnt + 31) >> 5;
        #pragma unroll
        for (int t = 0; t < 8; t++) {
            int p = t * 32 + lane;
            vals[t] = (t < nslot && p < cnt) ? g_perm[start + p] : 0x7FFFFFFF;
        }
        for (int it = 0; it < cnt; it++) {
            int m = 0x7FFFFFFF, mt = -1;
            #pragma unroll
            for (int t = 0; t < 8; t++)
                if (vals[t] < m) { m = vals[t]; mt = t; }
            int gm = __reduce_min_sync(0xFFFFFFFFu, m);
            if (m == gm && mt >= 0) vals[mt] = 0x7FFFFFFF;
            accum1(gm);
        }
    } else {
        for (int j = 0; j < cnt; j++) accum1(g_perm[start + j]);
    }

    __half2* dsth = (__half2*)(g_aggh + (size_t)seg * DIM);
    dsth[2 * lane]           = __floats2half2_rn(a0.x, a0.y);
    dsth[2 * lane + 1]       = __floats2half2_rn(a0.z, a0.w);
    dsth[64 + 2 * lane]      = __floats2half2_rn(a1.x, a1.y);
    dsth[64 + 2 * lane + 1]  = __floats2half2_rn(a1.z, a1.w);
    dsth[128 + 2 * lane]     = __floats2half2_rn(a2.x, a2.y);
    dsth[128 + 2 * lane + 1] = __floats2half2_rn(a2.z, a2.w);
    dsth[192 + 2 * lane]     = __floats2half2_rn(a3.x, a3.y);
    dsth[192 + 2 * lane + 1] = __floats2half2_rn(a3.z, a3.w);

    __threadfence();                       // publish this segment, then flag it
    if (lane == 0) atomicAdd(&g_mdone[seg >> 7], 1);
}

// BM=128, BN=128, BK=64, 256 threads (8 warps, 2Mx4N, warp tile 64x32)
__device__ void gemm_role(const float* __restrict__ linb, float* __restrict__ out,
                          char* sm, int tid, int gi) {
    int lane = tid & 31, wid = tid >> 5;
    int mtile = gi >> 2, ntile = gi & 3;

    if (tid == 0) {
        while (*((volatile int*)&g_mdone[mtile]) < 128) __nanosleep(200);
        __threadfence();
    }
    __syncthreads();

    const __half* Ag = g_aggh  + (size_t)mtile * 128 * DIM;
    const __half* Bg = g_linwh + (size_t)ntile * 128 * DIM;
    uint32_t sbase = (uint32_t)__cvta_generic_to_shared(sm);

    auto load_tile = [&](int kb, int buf) {
        uint32_t as = sbase + (uint32_t)(buf * ATILEB);
        uint32_t bs = sbase + (uint32_t)(2 * ATILEB + buf * BTILEB);
        #pragma unroll
        for (int j = 0; j < 4; j++) {      // A: 128 rows x 64 halves = 1024 x 16B
            int e = j * 256 + tid;
            int row = e >> 3, c = e & 7;
            cp16(as + (uint32_t)(row * PADH + c * 8) * 2,
                 Ag + (size_t)row * DIM + kb * BK + c * 8);
        }
        #pragma unroll
        for (int j = 0; j < 4; j++) {      // B: 128 rows x 64 halves = 1024 x 16B
            int e = j * 256 + tid;
            int n = e >> 3, c = e & 7;
            cp16(bs + (uint32_t)(n * PADH + c * 8) * 2,
                 Bg + (size_t)n * DIM + kb * BK + c * 8);
        }
        asm volatile("cp.async.commit_group;" ::: "memory");
    };

    int wm = (wid & 1) * 64;
    int wn = (wid >> 1) * 32;
    float acc[4][4][4];
    #pragma unroll
    for (int mi = 0; mi < 4; mi++)
        #pragma unroll
        for (int ni = 0; ni < 4; ni++)
            #pragma unroll
            for (int q = 0; q < 4; q++) acc[mi][ni][q] = 0.f;

    load_tile(0, 0);
    const int NKB = DIM / BK;              // 8
    int rq = lane >> 2, cq = lane & 3;
    for (int kb = 0; kb < NKB; kb++) {
        if (kb + 1 < NKB) {
            load_tile(kb + 1, (kb + 1) & 1);
            asm volatile("cp.async.wait_group 1;" ::: "memory");
        } else {
            asm volatile("cp.async.wait_group 0;" ::: "memory");
        }
        __syncthreads();

        int buf = kb & 1;
        const uint32_t* As = (const uint32_t*)(sm + buf * ATILEB);
        const uint32_t* Bs = (const uint32_t*)(sm + 2 * ATILEB + buf * BTILEB);
        #pragma unroll
        for (int ks = 0; ks < BK / 16; ks++) {     // 4 K-steps of 16 halves
            int k0 = ks * 8;
            uint32_t bf[4][2];
            #pragma unroll
            for (int ni = 0; ni < 4; ni++) {
                int n = wn + ni * 8 + rq;
                bf[ni][0] = Bs[n * (PADH / 2) + k0 + cq];
                bf[ni][1] = Bs[n * (PADH / 2) + k0 + cq + 4];
            }
            #pragma unroll
            for (int mi = 0; mi < 4; mi++) {
                int r = wm + mi * 16 + rq;
                uint32_t fa0 = As[r * (PADH / 2) + k0 + cq];
                uint32_t fa1 = As[(r + 8) * (PADH / 2) + k0 + cq];
                uint32_t fa2 = As[r * (PADH / 2) + k0 + cq + 4];
                uint32_t fa3 = As[(r + 8) * (PADH / 2) + k0 + cq + 4];
                #pragma unroll
                for (int ni = 0; ni < 4; ni++)
                    mma_f16(acc[mi][ni][0], acc[mi][ni][1], acc[mi][ni][2], acc[mi][ni][3],
                            fa0, fa1, fa2, fa3, bf[ni][0], bf[ni][1]);
            }
        }
        __syncthreads();
    }

    #pragma unroll
    for (int mi = 0; mi < 4; mi++) {
        int r0 = mtile * 128 + wm + mi * 16 + rq;
        #pragma unroll
        for (int ni = 0; ni < 4; ni++) {
            int col = ntile * 128 + wn + ni * 8 + 2 * cq;
            float2 bv = __ldg((const float2*)(linb + col));
            float2 v0 = {acc[mi][ni][0] + bv.x, acc[mi][ni][1] + bv.y};
            float2 v1 = {acc[mi][ni][2] + bv.x, acc[mi][ni][3] + bv.y};
            *(float2*)(out + (size_t)r0 * DIM + col) = v0;
            *(float2*)(out + (size_t)(r0 + 8) * DIM + col) = v1;
        }
    }
}

__global__ void __launch_bounds__(256, 2)
fused_gg_kernel(const float* __restrict__ h, const float* __restrict__ w,
                const float* __restrict__ linb, float* __restrict__ out) {
    extern __shared__ char sm[];
    int bid = blockIdx.x, tid = threadIdx.x;
    // bid -> role mapping: LEAD gathers, then groups of (4 gather + 1 gemm), tail gemm
    const int NGRP = (NGB - LEAD) / 4;               // 1900 full groups
    int gather_id = -1, gemm_id = -1;
    if (bid < LEAD) {
        gather_id = bid;
    } else {
        int pos = bid - LEAD;
        int grp = pos / 5, r = pos - grp * 5;
        if (grp < NGRP) {
            if (r < 4) gather_id = LEAD + grp * 4 + r;
            else       gemm_id = grp;
        } else {
            gemm_id = NGRP + (bid - (LEAD + NGRP * 5));
        }
    }
    if (gather_id >= 0) gather_role(h, w, tid, gather_id);
    else                gemm_role(linb, out, sm, tid, gemm_id);
}

// ---------------- launch ----------------
extern "C" void kernel_launch(void* const* d_in, const int* in_sizes, int n_in,
                              void* d_out, int out_size) {
    const float* h     = (const float*)d_in[0];
    const float* w     = (const float*)d_in[1];
    const float* lin_w = (const float*)d_in[2];
    const float* lin_b = (const float*)d_in[3];
    const void*  idx   = d_in[4];
    float* out = (float*)d_out;

    zero_detect_roundw_kernel<<<(DIM * DIM + 255) / 256, 256>>>(
        (const unsigned int*)idx, lin_w);
    hist_kernel<<<(NROWS + 255) / 256, 256>>>(idx);
    scan1_kernel<<<256, 256>>>();
    scan2_kernel<<<1, 256>>>();
    scan3_kernel<<<256, 256>>>();
    scatter_kernel<<<(NROWS + 255) / 256, 256>>>(idx);

    static int smem_set = 0;
    if (!smem_set) {
        cudaFuncSetAttribute(fused_gg_kernel, cudaFuncAttributeMaxDynamicSharedMemorySize,
                             SMEM_BYTES);
        smem_set = 1;
    }
    fused_gg_kernel<<<NGB + NGEMM, 256, SMEM_BYTES>>>(h, w, lin_b, out);
}